// round 4
// baseline (speedup 1.0000x reference)
#include <cuda_runtime.h>
#include <cuda_bf16.h>
#include <cstdint>

#define NB 4
#define NS 1024
#define NHID 1024
#define NH 16
#define NDH 64
#define ATT_SCALE 0.125f

// ---------------- scratch (no allocations allowed) ----------------
__device__ float g_Q[NB * NH * NS * NDH];   // [B,H,S,DH]
__device__ float g_K[NB * NH * NS * NDH];
__device__ float g_V[NB * NH * NS * NDH];
__device__ float g_O[NB * NS * NHID];       // [B,S,H,DH] == [B,S,HID]
__device__ __nv_bfloat16 g_Ah[4096 * 1024];
__device__ __nv_bfloat16 g_Al[4096 * 1024];
__device__ __nv_bfloat16 g_Bh[1024 * 1024];
__device__ __nv_bfloat16 g_Bl[1024 * 1024];

// =================================================================
// helpers
// =================================================================
__device__ __forceinline__ uint32_t smem_u32(const void* p) {
    uint32_t a;
    asm("{ .reg .u64 t; cvta.to.shared.u64 t, %1; cvt.u32.u64 %0, t; }"
        : "=r"(a) : "l"(p));
    return a;
}
#define CP_ASYNC16(sp, gp) \
    asm volatile("cp.async.cg.shared.global [%0], [%1], 16;" :: "r"(sp), "l"(gp) : "memory")
#define CP_COMMIT() asm volatile("cp.async.commit_group;" ::: "memory")
#define CP_WAIT(n)  asm volatile("cp.async.wait_group %0;" :: "n"(n) : "memory")
#define LDSM4(r, a) \
    asm volatile("ldmatrix.sync.aligned.m8n8.x4.shared.b16 {%0,%1,%2,%3}, [%4];" \
                 : "=r"((r)[0]), "=r"((r)[1]), "=r"((r)[2]), "=r"((r)[3]) : "r"(a))

__device__ __forceinline__ void mma_bf16(float* d, const uint32_t* a, const uint32_t* b) {
    asm volatile(
        "mma.sync.aligned.m16n8k16.row.col.f32.bf16.bf16.f32 "
        "{%0,%1,%2,%3},{%4,%5,%6,%7},{%8,%9},{%0,%1,%2,%3};"
        : "+f"(d[0]), "+f"(d[1]), "+f"(d[2]), "+f"(d[3])
        : "r"(a[0]), "r"(a[1]), "r"(a[2]), "r"(a[3]), "r"(b[0]), "r"(b[1]));
}

__device__ __forceinline__ void split2(float v, __nv_bfloat16& h, __nv_bfloat16& l) {
    h = __float2bfloat16_rn(v);
    l = __float2bfloat16_rn(v - __bfloat162float(h));
}

// =================================================================
// conversion kernels: fp32 -> bf16 hi/lo
// =================================================================
__global__ __launch_bounds__(256) void split_f32(
    const float* __restrict__ A, __nv_bfloat16* __restrict__ H,
    __nv_bfloat16* __restrict__ L, int n)
{
    int i = (blockIdx.x * 256 + threadIdx.x) * 4;
    if (i >= n) return;
    float4 v = *(const float4*)&A[i];
    __nv_bfloat16 h[4], l[4];
    split2(v.x, h[0], l[0]); split2(v.y, h[1], l[1]);
    split2(v.z, h[2], l[2]); split2(v.w, h[3], l[3]);
    *(uint2*)&H[i] = *(uint2*)h;
    *(uint2*)&L[i] = *(uint2*)l;
}

// W[h][k][e] fp32 -> Wt[h*64+e][k] bf16 hi/lo (transpose + split)
__global__ __launch_bounds__(256) void splitW_proj(
    const float* __restrict__ W, __nv_bfloat16* __restrict__ Ht,
    __nv_bfloat16* __restrict__ Lt)
{
    __shared__ float t[32][33];
    const int k0 = blockIdx.x * 32;
    const int n0 = blockIdx.y * 32;
    const int h = n0 >> 6, e0 = n0 & 63;
    const int x = threadIdx.x & 31, y = threadIdx.x >> 5;
#pragma unroll
    for (int j = 0; j < 32; j += 8)
        t[y + j][x] = W[h * 65536 + (k0 + y + j) * 64 + e0 + x];
    __syncthreads();
#pragma unroll
    for (int j = 0; j < 32; j += 8) {
        float v = t[x][y + j];
        __nv_bfloat16 hi, lo;
        split2(v, hi, lo);
        size_t o = (size_t)(n0 + y + j) * 1024 + k0 + x;
        Ht[o] = hi;
        Lt[o] = lo;
    }
}

// =================================================================
// HMMA GEMM: C[4096x1024] = A x B^T + bias  (A [m][k], B [n][k], bf16 split)
// MODE 0: C row-major.  MODE 1: C[((b*16+h)*1024+s)*64+e]
// =================================================================
#define BK 32
#define PADE 40                   // padded row stride in bf16 elems (80 B)
#define TILE_E (128 * PADE)       // elems per tile matrix
#define TILE_B (TILE_E * 2)       // bytes
#define GH_SMEM (8 * TILE_B)      // 4 matrices x 2 stages = 81920 B

template <int MODE>
__global__ __launch_bounds__(256) void gemm_hmma(
    const __nv_bfloat16* __restrict__ Ah, const __nv_bfloat16* __restrict__ Al,
    const __nv_bfloat16* __restrict__ Bh, const __nv_bfloat16* __restrict__ Bl,
    const float* __restrict__ bias, float* __restrict__ C)
{
    extern __shared__ __align__(128) char gsm[];
    const uint32_t sb = smem_u32(gsm);
    const int tid = threadIdx.x;
    const int m0 = blockIdx.y * 128;
    const int n0 = blockIdx.x * 128;
    const int lane = tid & 31, w = tid >> 5;
    const int wm = w >> 2;   // 0..1
    const int wn = w & 3;    // 0..3
    const int lr = lane & 15;
    const int lcb = (lane >> 4) * 16;  // col chunk byte offset (0/16)

    const __nv_bfloat16* gmat[4] = {Ah, Al, Bh, Bl};
    const int rbase[4] = {m0, m0, n0, n0};

    float acc[4][4][4];
#pragma unroll
    for (int i = 0; i < 4; i++)
#pragma unroll
        for (int j = 0; j < 4; j++)
#pragma unroll
            for (int r = 0; r < 4; r++) acc[i][j][r] = 0.f;

    // precomputed ldmatrix byte offsets within a tile
    uint32_t aoff[4], boff[2];
#pragma unroll
    for (int i = 0; i < 4; i++)
        aoff[i] = (uint32_t)((wm * 64 + i * 16 + lr) * 80) + lcb;
#pragma unroll
    for (int hlf = 0; hlf < 2; hlf++)
        boff[hlf] = (uint32_t)((wn * 32 + hlf * 16 + lr) * 80) + lcb;

    // ---- stage loader ----
    auto load_stage = [&](int s) {
        const int buf = s & 1;
        const int k0 = s * BK;
#pragma unroll
        for (int mat = 0; mat < 4; mat++) {
            const __nv_bfloat16* g = gmat[mat];
            uint32_t sbase = sb + (uint32_t)(buf * 4 + mat) * TILE_B;
#pragma unroll
            for (int i = 0; i < 2; i++) {
                int idx = tid + 256 * i;        // 0..511
                int row = idx >> 2;             // 0..127
                int ch = idx & 3;               // 16B chunk
                const void* gp = g + (size_t)(rbase[mat] + row) * 1024 + k0 + ch * 8;
                uint32_t sp = sbase + (uint32_t)(row * 80 + ch * 16);
                CP_ASYNC16(sp, gp);
            }
        }
        CP_COMMIT();
    };

    load_stage(0);

    for (int s = 0; s < 32; s++) {
        if (s + 1 < 32) {
            load_stage(s + 1);
            CP_WAIT(1);
        } else {
            CP_WAIT(0);
        }
        __syncthreads();

        const int buf = s & 1;
        const uint32_t base = sb + (uint32_t)buf * 4 * TILE_B;
#pragma unroll
        for (int kk = 0; kk < 2; kk++) {
            const uint32_t kb = kk * 32;  // 16 elems = 32 bytes
            uint32_t ah[4][4], al[4][4];
#pragma unroll
            for (int i = 0; i < 4; i++) {
                LDSM4(ah[i], base + aoff[i] + kb);
                LDSM4(al[i], base + TILE_B + aoff[i] + kb);
            }
            uint32_t bh[4][2], bl[4][2];
#pragma unroll
            for (int hlf = 0; hlf < 2; hlf++) {
                uint32_t r[4];
                LDSM4(r, base + 2 * TILE_B + boff[hlf] + kb);
                bh[2 * hlf][0] = r[0]; bh[2 * hlf + 1][0] = r[1];
                bh[2 * hlf][1] = r[2]; bh[2 * hlf + 1][1] = r[3];
                LDSM4(r, base + 3 * TILE_B + boff[hlf] + kb);
                bl[2 * hlf][0] = r[0]; bl[2 * hlf + 1][0] = r[1];
                bl[2 * hlf][1] = r[2]; bl[2 * hlf + 1][1] = r[3];
            }
#pragma unroll
            for (int i = 0; i < 4; i++)
#pragma unroll
                for (int j = 0; j < 4; j++) {
                    mma_bf16(acc[i][j], ah[i], bh[j]);
                    mma_bf16(acc[i][j], ah[i], bl[j]);
                    mma_bf16(acc[i][j], al[i], bh[j]);
                }
        }
        __syncthreads();
    }

    // ---- epilogue ----
#pragma unroll
    for (int i = 0; i < 4; i++) {
#pragma unroll
        for (int j = 0; j < 4; j++) {
            int row = m0 + wm * 64 + i * 16 + (lane >> 2);
            int col = n0 + wn * 32 + j * 8 + (lane & 3) * 2;
            float b0 = bias[col], b1 = bias[col + 1];
            float2 v0 = make_float2(acc[i][j][0] + b0, acc[i][j][1] + b1);
            float2 v1 = make_float2(acc[i][j][2] + b0, acc[i][j][3] + b1);
            if (MODE == 0) {
                *(float2*)&C[(size_t)row * 1024 + col] = v0;
                *(float2*)&C[(size_t)(row + 8) * 1024 + col] = v1;
            } else {
                int h = col >> 6, e = col & 63;
                int b = row >> 10, sI = row & 1023;
                int b2 = (row + 8) >> 10, s2 = (row + 8) & 1023;
                *(float2*)&C[(((size_t)(b * 16 + h) * 1024 + sI) << 6) + e] = v0;
                *(float2*)&C[(((size_t)(b2 * 16 + h) * 1024 + s2) << 6) + e] = v1;
            }
        }
    }
}

// =================================================================
// Fused relation-aware attention (unchanged from round 1).
// =================================================================
#define BQ 32
#define KT 128
#define PADR 68
#define SMEM_FLOATS (32*1024 + 128*PADR + 32*PADR + 33*PADR + 33*PADR + 32*33 + 32*33 + 32)
#define SMEM_BYTES (SMEM_FLOATS * 4)

__global__ __launch_bounds__(256) void attn_kernel(
    const float* __restrict__ Q, const float* __restrict__ K,
    const float* __restrict__ V, const float* __restrict__ relk,
    const float* __restrict__ relv, float* __restrict__ O)
{
    extern __shared__ float sm[];
    float* sS  = sm;
    float* sKV = sS + 32 * 1024;
    float* sQ  = sKV + 128 * PADR;
    float* sRK = sQ + 32 * PADR;
    float* sRV = sRK + 33 * PADR;
    float* sR  = sRV + 33 * PADR;
    float* sW  = sR + 32 * 33;
    float* sIL = sW + 32 * 33;

    const int tid = threadIdx.x;
    const int q0 = blockIdx.x * BQ;
    const int bh = blockIdx.z * NH + blockIdx.y;
    const int base = bh * (NS * NDH);

    {
        int idx = tid;
#pragma unroll
        for (int r = 0; r < 2; r++, idx += 256) {
            int row = idx >> 4, e4 = (idx & 15) << 2;
            *(float4*)&sQ[row * PADR + e4] =
                *(const float4*)&Q[base + (q0 + row) * 64 + e4];
        }
    }
    for (int idx = tid; idx < 33 * 16; idx += 256) {
        int row = idx >> 4, e4 = (idx & 15) << 2;
        *(float4*)&sRK[row * PADR + e4] = *(const float4*)&relk[row * 64 + e4];
        *(float4*)&sRV[row * PADR + e4] = *(const float4*)&relv[row * 64 + e4];
    }
    __syncthreads();

    for (int idx = tid; idx < 32 * 33; idx += 256) {
        int q = idx / 33, d = idx - q * 33;
        float s = 0.f;
#pragma unroll
        for (int e = 0; e < 64; e++) s += sQ[q * PADR + e] * sRK[d * PADR + e];
        sR[idx] = s;
    }
    __syncthreads();

    const int tx = tid & 31, ty = tid >> 5;

    for (int kt = 0; kt < 8; kt++) {
        int k0 = kt * KT;
        float4 tmp[8];
#pragma unroll
        for (int r = 0; r < 8; r++) {
            int idx = tid + 256 * r;
            int row = idx >> 4, e4 = (idx & 15) << 2;
            tmp[r] = *(const float4*)&K[base + (k0 + row) * 64 + e4];
        }
        __syncthreads();
#pragma unroll
        for (int r = 0; r < 8; r++) {
            int idx = tid + 256 * r;
            int row = idx >> 4, e4 = (idx & 15) << 2;
            *(float4*)&sKV[row * PADR + e4] = tmp[r];
        }
        __syncthreads();

        float c[4][4];
#pragma unroll
        for (int i = 0; i < 4; i++)
#pragma unroll
            for (int j = 0; j < 4; j++) c[i][j] = 0.f;
#pragma unroll
        for (int e4 = 0; e4 < 16; e4++) {
            float4 aq[4], bk[4];
#pragma unroll
            for (int i = 0; i < 4; i++)
                aq[i] = *(float4*)&sQ[(4 * ty + i) * PADR + e4 * 4];
#pragma unroll
            for (int j = 0; j < 4; j++)
                bk[j] = *(float4*)&sKV[(tx + 32 * j) * PADR + e4 * 4];
#pragma unroll
            for (int i = 0; i < 4; i++)
#pragma unroll
                for (int j = 0; j < 4; j++)
                    c[i][j] += aq[i].x * bk[j].x + aq[i].y * bk[j].y +
                               aq[i].z * bk[j].z + aq[i].w * bk[j].w;
        }
#pragma unroll
        for (int i = 0; i < 4; i++) {
            int q = 4 * ty + i;
            int qg = q0 + q;
#pragma unroll
            for (int j = 0; j < 4; j++) {
                int kg = k0 + tx + 32 * j;
                int dd = kg - qg;
                dd = dd < -16 ? -16 : (dd > 16 ? 16 : dd);
                sS[q * 1024 + kg] = (c[i][j] + sR[q * 33 + dd + 16]) * ATT_SCALE;
            }
        }
    }
    __syncthreads();

    {
        int warp = tid >> 5, lane = tid & 31;
        for (int rr = 0; rr < 4; rr++) {
            int r = warp * 4 + rr;
            int qg = q0 + r;
            float m = -1e30f;
            for (int k = lane; k < 1024; k += 32) m = fmaxf(m, sS[r * 1024 + k]);
#pragma unroll
            for (int o = 16; o > 0; o >>= 1)
                m = fmaxf(m, __shfl_xor_sync(0xffffffffu, m, o));
            float l = 0.f, w0 = 0.f, w32 = 0.f;
            for (int k = lane; k < 1024; k += 32) {
                float p = __expf(sS[r * 1024 + k] - m);
                sS[r * 1024 + k] = p;
                l += p;
                if (k <= qg - 16) w0 += p;
                if (k >= qg + 16) w32 += p;
            }
#pragma unroll
            for (int o = 16; o > 0; o >>= 1) {
                l += __shfl_xor_sync(0xffffffffu, l, o);
                w0 += __shfl_xor_sync(0xffffffffu, w0, o);
                w32 += __shfl_xor_sync(0xffffffffu, w32, o);
            }
            if (lane == 0) {
                sIL[r] = 1.f / l;
                sW[r * 33 + 0] = w0;
                sW[r * 33 + 32] = w32;
            }
        }
    }
    __syncthreads();
    for (int idx = tid; idx < 32 * 31; idx += 256) {
        int q = idx / 31, d = idx - q * 31 + 1;
        int k = q0 + q + d - 16;
        sW[q * 33 + d] = (k >= 0 && k < 1024) ? sS[q * 1024 + k] : 0.f;
    }
    __syncthreads();

    const int cx = tid & 31, cy = tid >> 5;
    float acc[4][2];
#pragma unroll
    for (int i = 0; i < 4; i++) { acc[i][0] = 0.f; acc[i][1] = 0.f; }

    for (int kt = 0; kt < 8; kt++) {
        int k0 = kt * KT;
        float4 tmp[8];
#pragma unroll
        for (int r = 0; r < 8; r++) {
            int idx = tid + 256 * r;
            int row = idx >> 4, e4 = (idx & 15) << 2;
            tmp[r] = *(const float4*)&V[base + (k0 + row) * 64 + e4];
        }
        __syncthreads();
#pragma unroll
        for (int r = 0; r < 8; r++) {
            int idx = tid + 256 * r;
            int row = idx >> 4, e4 = (idx & 15) << 2;
            *(float4*)&sKV[row * PADR + e4] = tmp[r];
        }
        __syncthreads();
#pragma unroll 4
        for (int kk = 0; kk < KT; kk += 4) {
            float4 p4[4];
#pragma unroll
            for (int i = 0; i < 4; i++)
                p4[i] = *(float4*)&sS[(4 * cy + i) * 1024 + k0 + kk];
            float v0[4], v1[4];
#pragma unroll
            for (int u = 0; u < 4; u++) {
                v0[u] = sKV[(kk + u) * PADR + cx];
                v1[u] = sKV[(kk + u) * PADR + cx + 32];
            }
#pragma unroll
            for (int i = 0; i < 4; i++) {
                acc[i][0] += p4[i].x * v0[0] + p4[i].y * v0[1] +
                             p4[i].z * v0[2] + p4[i].w * v0[3];
                acc[i][1] += p4[i].x * v1[0] + p4[i].y * v1[1] +
                             p4[i].z * v1[2] + p4[i].w * v1[3];
            }
        }
    }

#pragma unroll
    for (int i = 0; i < 4; i++) {
        int q = 4 * cy + i;
        float a0 = acc[i][0], a1 = acc[i][1];
#pragma unroll
        for (int d = 0; d < 33; d++) {
            float wv = sW[q * 33 + d];
            a0 += wv * sRV[d * PADR + cx];
            a1 += wv * sRV[d * PADR + cx + 32];
        }
        float il = sIL[q];
        int qg = q0 + q;
        int o = ((blockIdx.z * 1024 + qg) * 16 + blockIdx.y) * 64;
        O[o + cx] = a0 * il;
        O[o + cx + 32] = a1 * il;
    }
}

// =================================================================
extern "C" void kernel_launch(void* const* d_in, const int* in_sizes, int n_in,
                              void* d_out, int out_size)
{
    const float* query = (const float*)d_in[0];
    const float* key   = (const float*)d_in[1];
    const float* value = (const float*)d_in[2];
    const float* Wq    = (const float*)d_in[3];
    const float* bq    = (const float*)d_in[4];
    const float* Wk    = (const float*)d_in[5];
    const float* bk    = (const float*)d_in[6];
    const float* Wv    = (const float*)d_in[7];
    const float* bv    = (const float*)d_in[8];
    const float* relk  = (const float*)d_in[9];
    const float* relv  = (const float*)d_in[10];
    const float* fcW   = (const float*)d_in[11];
    const float* fcb   = (const float*)d_in[12];
    float* out = (float*)d_out;

    float *Qp, *Kp, *Vp, *Op;
    __nv_bfloat16 *Ah, *Al, *Bh, *Bl;
    cudaGetSymbolAddress((void**)&Qp, g_Q);
    cudaGetSymbolAddress((void**)&Kp, g_K);
    cudaGetSymbolAddress((void**)&Vp, g_V);
    cudaGetSymbolAddress((void**)&Op, g_O);
    cudaGetSymbolAddress((void**)&Ah, g_Ah);
    cudaGetSymbolAddress((void**)&Al, g_Al);
    cudaGetSymbolAddress((void**)&Bh, g_Bh);
    cudaGetSymbolAddress((void**)&Bl, g_Bl);

    cudaFuncSetAttribute(gemm_hmma<0>,
                         cudaFuncAttributeMaxDynamicSharedMemorySize, GH_SMEM);
    cudaFuncSetAttribute(gemm_hmma<1>,
                         cudaFuncAttributeMaxDynamicSharedMemorySize, GH_SMEM);
    cudaFuncSetAttribute(attn_kernel,
                         cudaFuncAttributeMaxDynamicSharedMemorySize, SMEM_BYTES);

    dim3 gg(8, 32);
    dim3 tw(32, 32);

    // Q = query @ Wq + bq
    splitW_proj<<<tw, 256>>>(Wq, Bh, Bl);
    split_f32<<<4096, 256>>>(query, Ah, Al, 4096 * 1024);
    gemm_hmma<1><<<gg, 256, GH_SMEM>>>(Ah, Al, Bh, Bl, bq, Qp);

    // K
    splitW_proj<<<tw, 256>>>(Wk, Bh, Bl);
    split_f32<<<4096, 256>>>(key, Ah, Al, 4096 * 1024);
    gemm_hmma<1><<<gg, 256, GH_SMEM>>>(Ah, Al, Bh, Bl, bk, Kp);

    // V
    splitW_proj<<<tw, 256>>>(Wv, Bh, Bl);
    split_f32<<<4096, 256>>>(value, Ah, Al, 4096 * 1024);
    gemm_hmma<1><<<gg, 256, GH_SMEM>>>(Ah, Al, Bh, Bl, bv, Vp);

    // attention
    attn_kernel<<<dim3(NS / BQ, NH, NB), 256, SMEM_BYTES>>>(Qp, Kp, Vp, relk, relv, Op);

    // fc: out = O @ fcW^T + fcb   (fcW is [n][k] row-major already)
    split_f32<<<1024, 256>>>(fcW, Bh, Bl, 1024 * 1024);
    split_f32<<<4096, 256>>>(Op, Ah, Al, 4096 * 1024);
    gemm_hmma<0><<<gg, 256, GH_SMEM>>>(Ah, Al, Bh, Bl, fcb, out);
}

// round 5
// speedup vs baseline: 1.5908x; 1.5908x over previous
#include <cuda_runtime.h>
#include <cuda_bf16.h>
#include <cstdint>

#define NB 4
#define NS 1024
#define NH 16
#define NDH 64
#define ATT_SCALE 0.125f
typedef __nv_bfloat16 bf16;

// ---------------- scratch ----------------
__device__ bf16 g_Qh[NB * NH * NS * NDH];
__device__ bf16 g_Ql[NB * NH * NS * NDH];
__device__ bf16 g_Kh[NB * NH * NS * NDH];
__device__ bf16 g_Kl[NB * NH * NS * NDH];
__device__ bf16 g_Vh[NB * NH * NS * NDH];
__device__ bf16 g_Vl[NB * NH * NS * NDH];
__device__ bf16 g_Oh[4096 * 1024];
__device__ bf16 g_Ol[4096 * 1024];
__device__ bf16 g_Bh[1024 * 1024];
__device__ bf16 g_Bl[1024 * 1024];

// ---------------- helpers ----------------
__device__ __forceinline__ uint32_t smem_u32(const void* p) {
    uint32_t a;
    asm("{ .reg .u64 t; cvta.to.shared.u64 t, %1; cvt.u32.u64 %0, t; }"
        : "=r"(a) : "l"(p));
    return a;
}
#define CP_ASYNC16(sp, gp) \
    asm volatile("cp.async.cg.shared.global [%0], [%1], 16;" :: "r"(sp), "l"(gp) : "memory")
#define CP_COMMIT() asm volatile("cp.async.commit_group;" ::: "memory")
#define CP_WAIT(n)  asm volatile("cp.async.wait_group %0;" :: "n"(n) : "memory")
#define LDSM4(r, a) \
    asm volatile("ldmatrix.sync.aligned.m8n8.x4.shared.b16 {%0,%1,%2,%3}, [%4];" \
                 : "=r"((r)[0]), "=r"((r)[1]), "=r"((r)[2]), "=r"((r)[3]) : "r"(a))
#define LDSM4T(r, a) \
    asm volatile("ldmatrix.sync.aligned.m8n8.x4.trans.shared.b16 {%0,%1,%2,%3}, [%4];" \
                 : "=r"((r)[0]), "=r"((r)[1]), "=r"((r)[2]), "=r"((r)[3]) : "r"(a))

__device__ __forceinline__ void mma_bf16(float* d, const uint32_t* a, const uint32_t* b) {
    asm volatile(
        "mma.sync.aligned.m16n8k16.row.col.f32.bf16.bf16.f32 "
        "{%0,%1,%2,%3},{%4,%5,%6,%7},{%8,%9},{%0,%1,%2,%3};"
        : "+f"(d[0]), "+f"(d[1]), "+f"(d[2]), "+f"(d[3])
        : "r"(a[0]), "r"(a[1]), "r"(a[2]), "r"(a[3]), "r"(b[0]), "r"(b[1]));
}
__device__ __forceinline__ void split2(float v, bf16& h, bf16& l) {
    h = __float2bfloat16_rn(v);
    l = __float2bfloat16_rn(v - __bfloat162float(h));
}
__device__ __forceinline__ uint32_t pack_hi(float a, float b) {
    __nv_bfloat162 t(__float2bfloat16_rn(a), __float2bfloat16_rn(b));
    return *(uint32_t*)&t;
}
__device__ __forceinline__ uint32_t pack_lo(float a, float b) {
    bf16 ha = __float2bfloat16_rn(a), hb = __float2bfloat16_rn(b);
    __nv_bfloat162 t(__float2bfloat16_rn(a - __bfloat162float(ha)),
                     __float2bfloat16_rn(b - __bfloat162float(hb)));
    return *(uint32_t*)&t;
}

// ---------------- prep kernels ----------------
__global__ __launch_bounds__(256) void split_f32(
    const float* __restrict__ A, bf16* __restrict__ H, bf16* __restrict__ L, int n)
{
    int i = (blockIdx.x * 256 + threadIdx.x) * 4;
    if (i >= n) return;
    float4 v = *(const float4*)&A[i];
    bf16 h[4], l[4];
    split2(v.x, h[0], l[0]); split2(v.y, h[1], l[1]);
    split2(v.z, h[2], l[2]); split2(v.w, h[3], l[3]);
    *(uint2*)&H[i] = *(uint2*)h;
    *(uint2*)&L[i] = *(uint2*)l;
}

__global__ __launch_bounds__(256) void splitW_proj(
    const float* __restrict__ W, bf16* __restrict__ Ht, bf16* __restrict__ Lt)
{
    __shared__ float t[32][33];
    const int k0 = blockIdx.x * 32, n0 = blockIdx.y * 32;
    const int h = n0 >> 6, e0 = n0 & 63;
    const int x = threadIdx.x & 31, y = threadIdx.x >> 5;
#pragma unroll
    for (int j = 0; j < 32; j += 8)
        t[y + j][x] = W[h * 65536 + (k0 + y + j) * 64 + e0 + x];
    __syncthreads();
#pragma unroll
    for (int j = 0; j < 32; j += 8) {
        bf16 hi, lo;
        split2(t[x][y + j], hi, lo);
        size_t o = (size_t)(n0 + y + j) * 1024 + k0 + x;
        Ht[o] = hi; Lt[o] = lo;
    }
}

// =================================================================
// HMMA GEMM.  ASPLIT=1: A fp32, split in-kernel.  ASPLIT=0: A bf16 hi/lo.
// MODE 0: fp32 C row-major.  MODE 1: bf16 hi/lo at [B,H,S,DH].
// =================================================================
#define BK 32
#define TILE_B (128 * 80)
#define GH_SMEM (8 * TILE_B)

template <int ASPLIT, int MODE>
__global__ __launch_bounds__(256) void gemm_hmma(
    const float* __restrict__ A32,
    const bf16* __restrict__ Abh, const bf16* __restrict__ Abl,
    const bf16* __restrict__ Bh, const bf16* __restrict__ Bl,
    const float* __restrict__ bias, float* __restrict__ C,
    bf16* __restrict__ Ch, bf16* __restrict__ Cl)
{
    extern __shared__ __align__(128) char dynsm[];
    const uint32_t sb = smem_u32(dynsm);
    const int tid = threadIdx.x;
    const int m0 = blockIdx.y * 128, n0 = blockIdx.x * 128;
    const int lane = tid & 31, w = tid >> 5;
    const int wm = w >> 2, wn = w & 3;
    const int lr = lane & 15, lcb = (lane >> 4) * 16;

    float acc[4][4][4];
#pragma unroll
    for (int i = 0; i < 4; i++)
#pragma unroll
        for (int j = 0; j < 4; j++)
#pragma unroll
            for (int r = 0; r < 4; r++) acc[i][j][r] = 0.f;

    uint32_t aoff[4], boff[2];
#pragma unroll
    for (int i = 0; i < 4; i++)
        aoff[i] = (uint32_t)((wm * 64 + i * 16 + lr) * 80) + lcb;
#pragma unroll
    for (int hlf = 0; hlf < 2; hlf++)
        boff[hlf] = (uint32_t)((wn * 32 + hlf * 16 + lr) * 80) + lcb;

    const int a_row = tid >> 1, a_chb = (tid & 1) * 4;
    float4 areg[4];
    auto ldgA = [&](int s) {
#pragma unroll
        for (int i = 0; i < 4; i++)
            areg[i] = *(const float4*)&A32[(size_t)(m0 + a_row) * 1024 + s * BK + (a_chb + i) * 4];
    };
    auto cvtA = [&](int buf) {
        char* ph = dynsm + (size_t)(buf * 4 + 0) * TILE_B;
        char* pl = dynsm + (size_t)(buf * 4 + 1) * TILE_B;
#pragma unroll
        for (int i = 0; i < 4; i++) {
            float4 v = areg[i];
            uint32_t off = (uint32_t)(a_row * 80 + (a_chb + i) * 8);
            *(uint2*)(ph + off) = make_uint2(pack_hi(v.x, v.y), pack_hi(v.z, v.w));
            *(uint2*)(pl + off) = make_uint2(pack_lo(v.x, v.y), pack_lo(v.z, v.w));
        }
    };
    auto cpStage = [&](int s) {
        const int buf = s & 1, k0 = s * BK;
        if (ASPLIT == 0) {
#pragma unroll
            for (int mat = 0; mat < 2; mat++) {
                const bf16* g = mat ? Abl : Abh;
                uint32_t sbase = sb + (uint32_t)(buf * 4 + mat) * TILE_B;
#pragma unroll
                for (int i = 0; i < 2; i++) {
                    int idx = tid + 256 * i, row = idx >> 2, ch = idx & 3;
                    CP_ASYNC16(sbase + (uint32_t)(row * 80 + ch * 16),
                               g + (size_t)(m0 + row) * 1024 + k0 + ch * 8);
                }
            }
        }
#pragma unroll
        for (int mat = 0; mat < 2; mat++) {
            const bf16* g = mat ? Bl : Bh;
            uint32_t sbase = sb + (uint32_t)(buf * 4 + 2 + mat) * TILE_B;
#pragma unroll
            for (int i = 0; i < 2; i++) {
                int idx = tid + 256 * i, row = idx >> 2, ch = idx & 3;
                CP_ASYNC16(sbase + (uint32_t)(row * 80 + ch * 16),
                           g + (size_t)(n0 + row) * 1024 + k0 + ch * 8);
            }
        }
        CP_COMMIT();
    };

    if (ASPLIT) ldgA(0);
    cpStage(0);
    if (ASPLIT) cvtA(0);

    for (int s = 0; s < 32; s++) {
        if (s < 31) {
            if (ASPLIT) ldgA(s + 1);
            cpStage(s + 1);
            CP_WAIT(1);
        } else CP_WAIT(0);
        __syncthreads();

        const uint32_t base = sb + (uint32_t)(s & 1) * 4 * TILE_B;
#pragma unroll
        for (int kk = 0; kk < 2; kk++) {
            const uint32_t kb = kk * 32;
            uint32_t ah[4][4], al[4][4];
#pragma unroll
            for (int i = 0; i < 4; i++) {
                LDSM4(ah[i], base + aoff[i] + kb);
                LDSM4(al[i], base + TILE_B + aoff[i] + kb);
            }
            uint32_t bh[4][2], bl[4][2];
#pragma unroll
            for (int hlf = 0; hlf < 2; hlf++) {
                uint32_t r[4];
                LDSM4(r, base + 2 * TILE_B + boff[hlf] + kb);
                bh[2*hlf][0] = r[0]; bh[2*hlf+1][0] = r[1];
                bh[2*hlf][1] = r[2]; bh[2*hlf+1][1] = r[3];
                LDSM4(r, base + 3 * TILE_B + boff[hlf] + kb);
                bl[2*hlf][0] = r[0]; bl[2*hlf+1][0] = r[1];
                bl[2*hlf][1] = r[2]; bl[2*hlf+1][1] = r[3];
            }
#pragma unroll
            for (int i = 0; i < 4; i++)
#pragma unroll
                for (int j = 0; j < 4; j++) {
                    mma_bf16(acc[i][j], ah[i], bh[j]);
                    mma_bf16(acc[i][j], ah[i], bl[j]);
                    mma_bf16(acc[i][j], al[i], bh[j]);
                }
        }
        __syncthreads();
        if (ASPLIT && s < 31) cvtA((s + 1) & 1);
    }

#pragma unroll
    for (int i = 0; i < 4; i++)
#pragma unroll
        for (int j = 0; j < 4; j++) {
            int row = m0 + wm * 64 + i * 16 + (lane >> 2);
            int col = n0 + wn * 32 + j * 8 + (lane & 3) * 2;
            float b0 = bias[col], b1 = bias[col + 1];
            float v00 = acc[i][j][0] + b0, v01 = acc[i][j][1] + b1;
            float v10 = acc[i][j][2] + b0, v11 = acc[i][j][3] + b1;
            if (MODE == 0) {
                *(float2*)&C[(size_t)row * 1024 + col] = make_float2(v00, v01);
                *(float2*)&C[(size_t)(row + 8) * 1024 + col] = make_float2(v10, v11);
            } else {
                int h = col >> 6, e = col & 63;
                int b = row >> 10, sI = row & 1023;
                size_t o0 = (((size_t)(b * 16 + h) * 1024 + sI) << 6) + e;
                size_t o1 = o0 + (8 << 6);
                *(uint32_t*)&Ch[o0] = pack_hi(v00, v01);
                *(uint32_t*)&Cl[o0] = pack_lo(v00, v01);
                *(uint32_t*)&Ch[o1] = pack_hi(v10, v11);
                *(uint32_t*)&Cl[o1] = pack_lo(v10, v11);
            }
        }
}

// =================================================================
// HMMA fused relation-aware attention.  CTA = (b, h, 128 q rows).
// =================================================================
#define AQH 0
#define AQL 18432
#define AKH 36864
#define AKL 55296
#define AVH 73728
#define AVL 92160
#define APH 110592
#define APL 145408
#define ARB 180224
#define AW  188672
#define ARK 205568
#define ARV 214016
#define ALP 222464
#define AWP 223488
#define AL_ 224512
#define ATT_SMEM 225024

__global__ __launch_bounds__(256) void attn_hmma(
    const bf16* __restrict__ Qh, const bf16* __restrict__ Ql,
    const bf16* __restrict__ Kh, const bf16* __restrict__ Kl,
    const bf16* __restrict__ Vh, const bf16* __restrict__ Vl,
    const float* __restrict__ relk, const float* __restrict__ relv,
    bf16* __restrict__ Oh, bf16* __restrict__ Ol)
{
    extern __shared__ __align__(128) char sm[];
    const uint32_t sb = smem_u32(sm);
    const int tid = threadIdx.x;
    const int lane = tid & 31, w = tid >> 5;
    const int q0 = blockIdx.x * 128;
    const size_t base = (size_t)(blockIdx.z * NH + blockIdx.y) * (NS * NDH);
    const int lr = lane & 15, hc = (lane >> 4) * 16;
    float* sW = (float*)(sm + AW);
    float* sRK = (float*)(sm + ARK);
    float* sRV = (float*)(sm + ARV);
    float* sLp = (float*)(sm + ALP);
    float* sWp = (float*)(sm + AWP);
    float* sL = (float*)(sm + AL_);

    auto ldTile = [&](uint32_t dh, uint32_t dl, const bf16* gh, const bf16* gl, int t) {
#pragma unroll
        for (int i = 0; i < 4; i++) {
            int idx = tid + 256 * i, row = idx >> 3, ch = idx & 7;
            size_t go = base + (size_t)(t * 128 + row) * 64 + ch * 8;
            uint32_t so = (uint32_t)(row * 144 + ch * 16);
            CP_ASYNC16(sb + dh + so, gh + go);
            CP_ASYNC16(sb + dl + so, gl + go);
        }
        CP_COMMIT();
    };

    // prologue: Q, K0, V0 in flight; rel tables + zero sW meanwhile
    {
#pragma unroll
        for (int i = 0; i < 4; i++) {
            int idx = tid + 256 * i, row = idx >> 3, ch = idx & 7;
            size_t go = base + (size_t)(q0 + row) * 64 + ch * 8;
            uint32_t so = (uint32_t)(row * 144 + ch * 16);
            CP_ASYNC16(sb + AQH + so, Qh + go);
            CP_ASYNC16(sb + AQL + so, Ql + go);
        }
        CP_COMMIT();
    }
    ldTile(AKH, AKL, Kh, Kl, 0);
    ldTile(AVH, AVL, Vh, Vl, 0);

    for (int i = tid; i < 33 * 64; i += 256) { sRK[i] = relk[i]; sRV[i] = relv[i]; }
    for (int i = tid; i < 128 * 33; i += 256) sW[i] = 0.f;

    CP_WAIT(2);
    __syncthreads();

    // r[q][d] = q . relk[d]
    {
        int q = tid >> 1;
        int d0 = (tid & 1) * 17, nd = (tid & 1) ? 16 : 17;
        float qv[64];
#pragma unroll
        for (int e2 = 0; e2 < 32; e2++) {
            uint32_t hv = *(uint32_t*)(sm + AQH + q * 144 + e2 * 4);
            uint32_t lv = *(uint32_t*)(sm + AQL + q * 144 + e2 * 4);
            float2 fh = __bfloat1622float2(*(__nv_bfloat162*)&hv);
            float2 fl = __bfloat1622float2(*(__nv_bfloat162*)&lv);
            qv[2 * e2] = fh.x + fl.x;
            qv[2 * e2 + 1] = fh.y + fl.y;
        }
        for (int d = d0; d < d0 + nd; d++) {
            float s = 0.f;
#pragma unroll
            for (int e = 0; e < 64; e++) s += qv[e] * sRK[d * 64 + e];
            *(bf16*)(sm + ARB + (q * 33 + d) * 2) = __float2bfloat16_rn(s);
        }
    }
    __syncthreads();

    const int wm = w >> 1, wn = w & 1;
    float acc2[8][4];
#pragma unroll
    for (int j = 0; j < 8; j++)
#pragma unroll
        for (int r = 0; r < 4; r++) acc2[j][r] = 0.f;
    float lsum[4] = {0.f, 0.f, 0.f, 0.f};
    float wsuf[4] = {0.f, 0.f, 0.f, 0.f};

    for (int t = 0; t < 8; t++) {
        CP_WAIT(1);            // K[t] done (V[t] may be pending)
        __syncthreads();

        // ---- QK phase ----
        float acc[2][8][4];
#pragma unroll
        for (int i = 0; i < 2; i++)
#pragma unroll
            for (int j = 0; j < 8; j++)
#pragma unroll
                for (int r = 0; r < 4; r++) acc[i][j][r] = 0.f;
#pragma unroll
        for (int es = 0; es < 4; es++) {
            uint32_t ah[2][4], al[2][4];
#pragma unroll
            for (int i = 0; i < 2; i++) {
                uint32_t ao = (uint32_t)((wm * 32 + i * 16 + lr) * 144) + hc + es * 32;
                LDSM4(ah[i], sb + AQH + ao);
                LDSM4(al[i], sb + AQL + ao);
            }
            uint32_t bh[8][2], bl[8][2];
#pragma unroll
            for (int c = 0; c < 4; c++) {
                uint32_t bo = (uint32_t)((wn * 64 + c * 16 + lr) * 144) + hc + es * 32;
                uint32_t r[4];
                LDSM4(r, sb + AKH + bo);
                bh[2*c][0] = r[0]; bh[2*c+1][0] = r[1];
                bh[2*c][1] = r[2]; bh[2*c+1][1] = r[3];
                LDSM4(r, sb + AKL + bo);
                bl[2*c][0] = r[0]; bl[2*c+1][0] = r[1];
                bl[2*c][1] = r[2]; bl[2*c+1][1] = r[3];
            }
#pragma unroll
            for (int i = 0; i < 2; i++)
#pragma unroll
                for (int j = 0; j < 8; j++) {
                    mma_bf16(acc[i][j], ah[i], bh[j]);
                    mma_bf16(acc[i][j], ah[i], bl[j]);
                    mma_bf16(acc[i][j], al[i], bh[j]);
                }
        }
        __syncthreads();        // all warps done reading K
        if (t < 7) ldTile(AKH, AKL, Kh, Kl, t + 1);

        // ---- softmax epilogue -> P (bf16 hi/lo) ----
        const int k0 = t * 128;
#pragma unroll
        for (int i = 0; i < 2; i++)
#pragma unroll
            for (int j = 0; j < 8; j++) {
                int row = wm * 32 + i * 16 + (lane >> 2);
                int col = wn * 64 + j * 8 + (lane & 3) * 2;
#pragma unroll
                for (int rh = 0; rh < 2; rh++) {
                    int rr = row + rh * 8;
                    int qg = q0 + rr;
                    float p01[2];
#pragma unroll
                    for (int v = 0; v < 2; v++) {
                        int kg = k0 + col + v;
                        int dd = kg - qg;
                        int dc = dd < -16 ? -16 : (dd > 16 ? 16 : dd);
                        float rb = __bfloat162float(
                            *(bf16*)(sm + ARB + (rr * 33 + dc + 16) * 2));
                        float p = __expf((acc[i][j][rh * 2 + v] + rb) * ATT_SCALE);
                        p01[v] = p;
                        lsum[i * 2 + rh] += p;
                        if (dd >= 16) wsuf[i * 2 + rh] += p;
                        else if (dd > -16) sW[rr * 33 + dd + 16] = p;
                    }
                    uint32_t po = (uint32_t)(rr * 272 + col * 2);
                    *(uint32_t*)(sm + APH + po) = pack_hi(p01[0], p01[1]);
                    *(uint32_t*)(sm + APL + po) = pack_lo(p01[0], p01[1]);
                }
            }
        __syncthreads();        // P visible
        if (t < 7) { CP_WAIT(1); } else { CP_WAIT(0); }   // V[t] done
        __syncthreads();

        // ---- PV phase ----
#pragma unroll
        for (int ks = 0; ks < 8; ks++) {
            uint32_t ph[4], pl[4];
            uint32_t po = (uint32_t)((w * 16 + lr) * 272) + ks * 32 + hc;
            LDSM4(ph, sb + APH + po);
            LDSM4(pl, sb + APL + po);
            uint32_t vh[8][2], vl[8][2];
#pragma unroll
            for (int c = 0; c < 4; c++) {
                uint32_t vo = (uint32_t)((ks * 16 + lr) * 144) + (c * 2 + (lane >> 4)) * 16;
                uint32_t r[4];
                LDSM4T(r, sb + AVH + vo);
                vh[2*c][0] = r[0]; vh[2*c][1] = r[1];
                vh[2*c+1][0] = r[2]; vh[2*c+1][1] = r[3];
                LDSM4T(r, sb + AVL + vo);
                vl[2*c][0] = r[0]; vl[2*c][1] = r[1];
                vl[2*c+1][0] = r[2]; vl[2*c+1][1] = r[3];
            }
#pragma unroll
            for (int j = 0; j < 8; j++) {
                mma_bf16(acc2[j], ph, vh[j]);
                mma_bf16(acc2[j], ph, vl[j]);
                mma_bf16(acc2[j], pl, vh[j]);
            }
        }
        __syncthreads();        // V consumed
        if (t < 7) ldTile(AVH, AVL, Vh, Vl, t + 1);
    }

    // ---- deterministic l / w32 reduction ----
#pragma unroll
    for (int i = 0; i < 4; i++) {
        lsum[i] += __shfl_xor_sync(0xffffffffu, lsum[i], 1);
        lsum[i] += __shfl_xor_sync(0xffffffffu, lsum[i], 2);
        wsuf[i] += __shfl_xor_sync(0xffffffffu, wsuf[i], 1);
        wsuf[i] += __shfl_xor_sync(0xffffffffu, wsuf[i], 2);
    }
    if ((lane & 3) == 0) {
#pragma unroll
        for (int i = 0; i < 4; i++) {
            int row = wm * 32 + (i >> 1) * 16 + (i & 1) * 8 + (lane >> 2);
            sLp[row * 2 + wn] = lsum[i];
            sWp[row * 2 + wn] = wsuf[i];
        }
    }
    __syncthreads();
    if (tid < 128) {
        int r = tid;
        float l = sLp[r * 2] + sLp[r * 2 + 1];
        float ws = sWp[r * 2] + sWp[r * 2 + 1];
        float mid = 0.f;
#pragma unroll
        for (int d = 1; d < 32; d++) mid += sW[r * 33 + d];
        sW[r * 33 + 0] = l - ws - mid;
        sW[r * 33 + 32] = ws;
        sL[r] = 1.f / l;
    }
    __syncthreads();

    // ---- rel_v bias + normalize + store O (bf16 hi/lo, [B,S,HID]) ----
#pragma unroll
    for (int j = 0; j < 8; j++) {
        int row0 = w * 16 + (lane >> 2), row1 = row0 + 8;
        int col = j * 8 + (lane & 3) * 2;
        float b00 = 0.f, b01 = 0.f, b10 = 0.f, b11 = 0.f;
#pragma unroll
        for (int d = 0; d < 33; d++) {
            float w0v = sW[row0 * 33 + d], w1v = sW[row1 * 33 + d];
            float r0 = sRV[d * 64 + col], r1 = sRV[d * 64 + col + 1];
            b00 += w0v * r0; b01 += w0v * r1;
            b10 += w1v * r0; b11 += w1v * r1;
        }
        float il0 = sL[row0], il1 = sL[row1];
        float o00 = (acc2[j][0] + b00) * il0, o01 = (acc2[j][1] + b01) * il0;
        float o10 = (acc2[j][2] + b10) * il1, o11 = (acc2[j][3] + b11) * il1;
        size_t g0 = ((size_t)(blockIdx.z * 1024 + q0 + row0)) * 1024 + blockIdx.y * 64 + col;
        size_t g1 = ((size_t)(blockIdx.z * 1024 + q0 + row1)) * 1024 + blockIdx.y * 64 + col;
        *(uint32_t*)&Oh[g0] = pack_hi(o00, o01);
        *(uint32_t*)&Ol[g0] = pack_lo(o00, o01);
        *(uint32_t*)&Oh[g1] = pack_hi(o10, o11);
        *(uint32_t*)&Ol[g1] = pack_lo(o10, o11);
    }
}

// =================================================================
extern "C" void kernel_launch(void* const* d_in, const int* in_sizes, int n_in,
                              void* d_out, int out_size)
{
    const float* query = (const float*)d_in[0];
    const float* key   = (const float*)d_in[1];
    const float* value = (const float*)d_in[2];
    const float* Wq    = (const float*)d_in[3];
    const float* bq    = (const float*)d_in[4];
    const float* Wk    = (const float*)d_in[5];
    const float* bk    = (const float*)d_in[6];
    const float* Wv    = (const float*)d_in[7];
    const float* bv    = (const float*)d_in[8];
    const float* relk  = (const float*)d_in[9];
    const float* relv  = (const float*)d_in[10];
    const float* fcW   = (const float*)d_in[11];
    const float* fcb   = (const float*)d_in[12];
    float* out = (float*)d_out;

    bf16 *Qh, *Ql, *Kh, *Kl, *Vh, *Vl, *Oh, *Ol, *Bh, *Bl;
    cudaGetSymbolAddress((void**)&Qh, g_Qh); cudaGetSymbolAddress((void**)&Ql, g_Ql);
    cudaGetSymbolAddress((void**)&Kh, g_Kh); cudaGetSymbolAddress((void**)&Kl, g_Kl);
    cudaGetSymbolAddress((void**)&Vh, g_Vh); cudaGetSymbolAddress((void**)&Vl, g_Vl);
    cudaGetSymbolAddress((void**)&Oh, g_Oh); cudaGetSymbolAddress((void**)&Ol, g_Ol);
    cudaGetSymbolAddress((void**)&Bh, g_Bh); cudaGetSymbolAddress((void**)&Bl, g_Bl);

    cudaFuncSetAttribute(gemm_hmma<1,1>, cudaFuncAttributeMaxDynamicSharedMemorySize, GH_SMEM);
    cudaFuncSetAttribute(gemm_hmma<0,0>, cudaFuncAttributeMaxDynamicSharedMemorySize, GH_SMEM);
    cudaFuncSetAttribute(attn_hmma, cudaFuncAttributeMaxDynamicSharedMemorySize, ATT_SMEM);

    dim3 gg(8, 32), tw(32, 32);

    splitW_proj<<<tw, 256>>>(Wq, Bh, Bl);
    gemm_hmma<1,1><<<gg, 256, GH_SMEM>>>(query, nullptr, nullptr, Bh, Bl, bq,
                                         nullptr, Qh, Ql);
    splitW_proj<<<tw, 256>>>(Wk, Bh, Bl);
    gemm_hmma<1,1><<<gg, 256, GH_SMEM>>>(key, nullptr, nullptr, Bh, Bl, bk,
                                         nullptr, Kh, Kl);
    splitW_proj<<<tw, 256>>>(Wv, Bh, Bl);
    gemm_hmma<1,1><<<gg, 256, GH_SMEM>>>(value, nullptr, nullptr, Bh, Bl, bv,
                                         nullptr, Vh, Vl);

    attn_hmma<<<dim3(8, NH, NB), 256, ATT_SMEM>>>(Qh, Ql, Kh, Kl, Vh, Vl,
                                                  relk, relv, Oh, Ol);

    split_f32<<<1024, 256>>>(fcW, Bh, Bl, 1024 * 1024);
    gemm_hmma<0,0><<<gg, 256, GH_SMEM>>>(nullptr, Oh, Ol, Bh, Bl, fcb,
                                         out, nullptr, nullptr);
}

// round 6
// speedup vs baseline: 1.8367x; 1.1545x over previous
#include <cuda_runtime.h>
#include <cuda_bf16.h>
#include <cstdint>

#define NB 4
#define NS 1024
#define NH 16
#define NDH 64
#define C2A 0.18033688f   // ATT_SCALE * log2(e)
typedef __nv_bfloat16 bf16;

// ---------------- scratch ----------------
__device__ bf16 g_Qh[NB * NH * NS * NDH];
__device__ bf16 g_Ql[NB * NH * NS * NDH];
__device__ bf16 g_Kh[NB * NH * NS * NDH];
__device__ bf16 g_Kl[NB * NH * NS * NDH];
__device__ bf16 g_Vh[NB * NH * NS * NDH];
__device__ bf16 g_Vl[NB * NH * NS * NDH];
__device__ bf16 g_Oh[4096 * 1024];
__device__ bf16 g_Ol[4096 * 1024];
__device__ bf16 g_Wh[3 * 1024 * 1024];
__device__ bf16 g_Wl[3 * 1024 * 1024];
__device__ bf16 g_Bh[1024 * 1024];
__device__ bf16 g_Bl[1024 * 1024];

// ---------------- helpers ----------------
__device__ __forceinline__ uint32_t smem_u32(const void* p) {
    uint32_t a;
    asm("{ .reg .u64 t; cvta.to.shared.u64 t, %1; cvt.u32.u64 %0, t; }"
        : "=r"(a) : "l"(p));
    return a;
}
#define CP_ASYNC16(sp, gp) \
    asm volatile("cp.async.cg.shared.global [%0], [%1], 16;" :: "r"(sp), "l"(gp) : "memory")
#define CP_COMMIT() asm volatile("cp.async.commit_group;" ::: "memory")
#define CP_WAIT(n)  asm volatile("cp.async.wait_group %0;" :: "n"(n) : "memory")
#define LDSM4(r, a) \
    asm volatile("ldmatrix.sync.aligned.m8n8.x4.shared.b16 {%0,%1,%2,%3}, [%4];" \
                 : "=r"((r)[0]), "=r"((r)[1]), "=r"((r)[2]), "=r"((r)[3]) : "r"(a))
#define LDSM4T(r, a) \
    asm volatile("ldmatrix.sync.aligned.m8n8.x4.trans.shared.b16 {%0,%1,%2,%3}, [%4];" \
                 : "=r"((r)[0]), "=r"((r)[1]), "=r"((r)[2]), "=r"((r)[3]) : "r"(a))

__device__ __forceinline__ void mma_bf16(float* d, const uint32_t* a, const uint32_t* b) {
    asm volatile(
        "mma.sync.aligned.m16n8k16.row.col.f32.bf16.bf16.f32 "
        "{%0,%1,%2,%3},{%4,%5,%6,%7},{%8,%9},{%0,%1,%2,%3};"
        : "+f"(d[0]), "+f"(d[1]), "+f"(d[2]), "+f"(d[3])
        : "r"(a[0]), "r"(a[1]), "r"(a[2]), "r"(a[3]), "r"(b[0]), "r"(b[1]));
}
__device__ __forceinline__ void split2(float v, bf16& h, bf16& l) {
    h = __float2bfloat16_rn(v);
    l = __float2bfloat16_rn(v - __bfloat162float(h));
}
__device__ __forceinline__ uint32_t pack_hi(float a, float b) {
    __nv_bfloat162 t(__float2bfloat16_rn(a), __float2bfloat16_rn(b));
    return *(uint32_t*)&t;
}
__device__ __forceinline__ uint32_t pack_lo(float a, float b) {
    bf16 ha = __float2bfloat16_rn(a), hb = __float2bfloat16_rn(b);
    __nv_bfloat162 t(__float2bfloat16_rn(a - __bfloat162float(ha)),
                     __float2bfloat16_rn(b - __bfloat162float(hb)));
    return *(uint32_t*)&t;
}

// ---------------- prep kernels ----------------
__global__ __launch_bounds__(256) void split_f32(
    const float* __restrict__ A, bf16* __restrict__ H, bf16* __restrict__ L, int n)
{
    int i = (blockIdx.x * 256 + threadIdx.x) * 4;
    if (i >= n) return;
    float4 v = *(const float4*)&A[i];
    bf16 h[4], l[4];
    split2(v.x, h[0], l[0]); split2(v.y, h[1], l[1]);
    split2(v.z, h[2], l[2]); split2(v.w, h[3], l[3]);
    *(uint2*)&H[i] = *(uint2*)h;
    *(uint2*)&L[i] = *(uint2*)l;
}

__global__ __launch_bounds__(256) void splitW3(
    const float* __restrict__ Wq, const float* __restrict__ Wk,
    const float* __restrict__ Wv, bf16* __restrict__ Ht, bf16* __restrict__ Lt)
{
    const float* W = blockIdx.z == 0 ? Wq : (blockIdx.z == 1 ? Wk : Wv);
    bf16* H = Ht + (size_t)blockIdx.z * 1048576;
    bf16* L = Lt + (size_t)blockIdx.z * 1048576;
    __shared__ float t[32][33];
    const int k0 = blockIdx.x * 32, n0 = blockIdx.y * 32;
    const int h = n0 >> 6, e0 = n0 & 63;
    const int x = threadIdx.x & 31, y = threadIdx.x >> 5;
#pragma unroll
    for (int j = 0; j < 32; j += 8)
        t[y + j][x] = W[h * 65536 + (k0 + y + j) * 64 + e0 + x];
    __syncthreads();
#pragma unroll
    for (int j = 0; j < 32; j += 8) {
        bf16 hi, lo;
        split2(t[x][y + j], hi, lo);
        size_t o = (size_t)(n0 + y + j) * 1024 + k0 + x;
        H[o] = hi; L[o] = lo;
    }
}

// =================================================================
// HMMA GEMM body.  ASPLIT=1: A fp32 (split in-kernel).  Else bf16 hi/lo.
// MODE 0: fp32 C row-major.  MODE 1: bf16 hi/lo at [B,H,S,DH].
// =================================================================
#define BK 32
#define TILE_B (128 * 80)
#define GH_SMEM (8 * TILE_B)

template <int ASPLIT, int MODE>
__device__ __forceinline__ void gemm_body(
    char* dynsm,
    const float* __restrict__ A32,
    const bf16* __restrict__ Abh, const bf16* __restrict__ Abl,
    const bf16* __restrict__ Bh, const bf16* __restrict__ Bl,
    const float* __restrict__ bias, float* __restrict__ C,
    bf16* __restrict__ Ch, bf16* __restrict__ Cl)
{
    const uint32_t sb = smem_u32(dynsm);
    const int tid = threadIdx.x;
    const int m0 = blockIdx.y * 128, n0 = blockIdx.x * 128;
    const int lane = tid & 31, w = tid >> 5;
    const int wm = w >> 2, wn = w & 3;
    const int lr = lane & 15, lcb = (lane >> 4) * 16;

    float acc[4][4][4];
#pragma unroll
    for (int i = 0; i < 4; i++)
#pragma unroll
        for (int j = 0; j < 4; j++)
#pragma unroll
            for (int r = 0; r < 4; r++) acc[i][j][r] = 0.f;

    uint32_t aoff[4], boff[2];
#pragma unroll
    for (int i = 0; i < 4; i++)
        aoff[i] = (uint32_t)((wm * 64 + i * 16 + lr) * 80) + lcb;
#pragma unroll
    for (int hlf = 0; hlf < 2; hlf++)
        boff[hlf] = (uint32_t)((wn * 32 + hlf * 16 + lr) * 80) + lcb;

    const int a_row = tid >> 1, a_chb = (tid & 1) * 4;
    float4 areg[4];
    auto ldgA = [&](int s) {
#pragma unroll
        for (int i = 0; i < 4; i++)
            areg[i] = *(const float4*)&A32[(size_t)(m0 + a_row) * 1024 + s * BK + (a_chb + i) * 4];
    };
    auto cvtA = [&](int buf) {
        char* ph = dynsm + (size_t)(buf * 4 + 0) * TILE_B;
        char* pl = dynsm + (size_t)(buf * 4 + 1) * TILE_B;
#pragma unroll
        for (int i = 0; i < 4; i++) {
            float4 v = areg[i];
            uint32_t off = (uint32_t)(a_row * 80 + (a_chb + i) * 8);
            *(uint2*)(ph + off) = make_uint2(pack_hi(v.x, v.y), pack_hi(v.z, v.w));
            *(uint2*)(pl + off) = make_uint2(pack_lo(v.x, v.y), pack_lo(v.z, v.w));
        }
    };
    auto cpStage = [&](int s) {
        const int buf = s & 1, k0 = s * BK;
        if (ASPLIT == 0) {
#pragma unroll
            for (int mat = 0; mat < 2; mat++) {
                const bf16* g = mat ? Abl : Abh;
                uint32_t sbase = sb + (uint32_t)(buf * 4 + mat) * TILE_B;
#pragma unroll
                for (int i = 0; i < 2; i++) {
                    int idx = tid + 256 * i, row = idx >> 2, ch = idx & 3;
                    CP_ASYNC16(sbase + (uint32_t)(row * 80 + ch * 16),
                               g + (size_t)(m0 + row) * 1024 + k0 + ch * 8);
                }
            }
        }
#pragma unroll
        for (int mat = 0; mat < 2; mat++) {
            const bf16* g = mat ? Bl : Bh;
            uint32_t sbase = sb + (uint32_t)(buf * 4 + 2 + mat) * TILE_B;
#pragma unroll
            for (int i = 0; i < 2; i++) {
                int idx = tid + 256 * i, row = idx >> 2, ch = idx & 3;
                CP_ASYNC16(sbase + (uint32_t)(row * 80 + ch * 16),
                           g + (size_t)(n0 + row) * 1024 + k0 + ch * 8);
            }
        }
        CP_COMMIT();
    };

    if (ASPLIT) ldgA(0);
    cpStage(0);
    if (ASPLIT) cvtA(0);

    for (int s = 0; s < 32; s++) {
        if (s < 31) {
            if (ASPLIT) ldgA(s + 1);
            cpStage(s + 1);
            CP_WAIT(1);
        } else CP_WAIT(0);
        __syncthreads();

        const uint32_t base = sb + (uint32_t)(s & 1) * 4 * TILE_B;
#pragma unroll
        for (int kk = 0; kk < 2; kk++) {
            const uint32_t kb = kk * 32;
            uint32_t ah[4][4], al[4][4];
#pragma unroll
            for (int i = 0; i < 4; i++) {
                LDSM4(ah[i], base + aoff[i] + kb);
                LDSM4(al[i], base + TILE_B + aoff[i] + kb);
            }
            uint32_t bh[4][2], bl[4][2];
#pragma unroll
            for (int hlf = 0; hlf < 2; hlf++) {
                uint32_t r[4];
                LDSM4(r, base + 2 * TILE_B + boff[hlf] + kb);
                bh[2*hlf][0] = r[0]; bh[2*hlf+1][0] = r[1];
                bh[2*hlf][1] = r[2]; bh[2*hlf+1][1] = r[3];
                LDSM4(r, base + 3 * TILE_B + boff[hlf] + kb);
                bl[2*hlf][0] = r[0]; bl[2*hlf+1][0] = r[1];
                bl[2*hlf][1] = r[2]; bl[2*hlf+1][1] = r[3];
            }
#pragma unroll
            for (int i = 0; i < 4; i++)
#pragma unroll
                for (int j = 0; j < 4; j++) {
                    mma_bf16(acc[i][j], ah[i], bh[j]);
                    mma_bf16(acc[i][j], ah[i], bl[j]);
                    mma_bf16(acc[i][j], al[i], bh[j]);
                }
        }
        __syncthreads();
        if (ASPLIT && s < 31) cvtA((s + 1) & 1);
    }

#pragma unroll
    for (int i = 0; i < 4; i++)
#pragma unroll
        for (int j = 0; j < 4; j++) {
            int row = m0 + wm * 64 + i * 16 + (lane >> 2);
            int col = n0 + wn * 32 + j * 8 + (lane & 3) * 2;
            float b0 = bias[col], b1 = bias[col + 1];
            float v00 = acc[i][j][0] + b0, v01 = acc[i][j][1] + b1;
            float v10 = acc[i][j][2] + b0, v11 = acc[i][j][3] + b1;
            if (MODE == 0) {
                *(float2*)&C[(size_t)row * 1024 + col] = make_float2(v00, v01);
                *(float2*)&C[(size_t)(row + 8) * 1024 + col] = make_float2(v10, v11);
            } else {
                int h = col >> 6, e = col & 63;
                int b = row >> 10, sI = row & 1023;
                size_t o0 = (((size_t)(b * 16 + h) * 1024 + sI) << 6) + e;
                size_t o1 = o0 + (8 << 6);
                *(uint32_t*)&Ch[o0] = pack_hi(v00, v01);
                *(uint32_t*)&Cl[o0] = pack_lo(v00, v01);
                *(uint32_t*)&Ch[o1] = pack_hi(v10, v11);
                *(uint32_t*)&Cl[o1] = pack_lo(v10, v11);
            }
        }
}

// fused Q/K/V projections (gridDim.z = 3 selects input set)
__global__ __launch_bounds__(256) void gemm_proj(
    const float* q, const float* k, const float* v,
    const bf16* Wh, const bf16* Wl,
    const float* bq, const float* bk, const float* bv,
    bf16* Qh, bf16* Ql, bf16* Kh, bf16* Kl, bf16* Vh, bf16* Vl)
{
    extern __shared__ __align__(128) char dynsm[];
    int z = blockIdx.z;
    const float* A = z == 0 ? q : (z == 1 ? k : v);
    const float* bias = z == 0 ? bq : (z == 1 ? bk : bv);
    bf16* Ch = z == 0 ? Qh : (z == 1 ? Kh : Vh);
    bf16* Cl = z == 0 ? Ql : (z == 1 ? Kl : Vl);
    gemm_body<1, 1>(dynsm, A, nullptr, nullptr,
                    Wh + (size_t)z * 1048576, Wl + (size_t)z * 1048576,
                    bias, nullptr, Ch, Cl);
}

__global__ __launch_bounds__(256) void gemm_fc(
    const bf16* Abh, const bf16* Abl, const bf16* Bh, const bf16* Bl,
    const float* bias, float* C)
{
    extern __shared__ __align__(128) char dynsm[];
    gemm_body<0, 0>(dynsm, nullptr, Abh, Abl, Bh, Bl, bias, C, nullptr, nullptr);
}

// =================================================================
// HMMA fused relation-aware attention.  CTA = (b, h, 128 q rows).
// =================================================================
#define AQH 0
#define AQL 18432
#define AKH 36864
#define AKL 55296
#define AVH 73728
#define AVL 92160
#define APH 110592
#define APL 145408
#define ARB 180224
#define AW  188672
#define ARK 205568
#define ARV 214016
#define ALP 222464
#define AWP 223488
#define AL_ 224512
#define ATT_SMEM 225024

__global__ __launch_bounds__(256) void attn_hmma(
    const bf16* __restrict__ Qh, const bf16* __restrict__ Ql,
    const bf16* __restrict__ Kh, const bf16* __restrict__ Kl,
    const bf16* __restrict__ Vh, const bf16* __restrict__ Vl,
    const float* __restrict__ relk, const float* __restrict__ relv,
    bf16* __restrict__ Oh, bf16* __restrict__ Ol)
{
    extern __shared__ __align__(128) char sm[];
    const uint32_t sb = smem_u32(sm);
    const int tid = threadIdx.x;
    const int lane = tid & 31, w = tid >> 5;
    const int q0 = blockIdx.x * 128;
    const size_t base = (size_t)(blockIdx.z * NH + blockIdx.y) * (NS * NDH);
    const int lr = lane & 15, hc = (lane >> 4) * 16;
    float* sW = (float*)(sm + AW);
    float* sRK = (float*)(sm + ARK);
    float* sRV = (float*)(sm + ARV);
    float* sLp = (float*)(sm + ALP);
    float* sWp = (float*)(sm + AWP);
    float* sL = (float*)(sm + AL_);

    auto ldTile = [&](uint32_t dh, uint32_t dl, const bf16* gh, const bf16* gl, int t) {
#pragma unroll
        for (int i = 0; i < 4; i++) {
            int idx = tid + 256 * i, row = idx >> 3, ch = idx & 7;
            size_t go = base + (size_t)(t * 128 + row) * 64 + ch * 8;
            uint32_t so = (uint32_t)(row * 144 + ch * 16);
            CP_ASYNC16(sb + dh + so, gh + go);
            CP_ASYNC16(sb + dl + so, gl + go);
        }
        CP_COMMIT();
    };

    {
#pragma unroll
        for (int i = 0; i < 4; i++) {
            int idx = tid + 256 * i, row = idx >> 3, ch = idx & 7;
            size_t go = base + (size_t)(q0 + row) * 64 + ch * 8;
            uint32_t so = (uint32_t)(row * 144 + ch * 16);
            CP_ASYNC16(sb + AQH + so, Qh + go);
            CP_ASYNC16(sb + AQL + so, Ql + go);
        }
        CP_COMMIT();
    }
    ldTile(AKH, AKL, Kh, Kl, 0);
    ldTile(AVH, AVL, Vh, Vl, 0);

    for (int i = tid; i < 33 * 64; i += 256) { sRK[i] = relk[i]; sRV[i] = relv[i]; }
    for (int i = tid; i < 128 * 33; i += 256) sW[i] = 0.f;

    CP_WAIT(2);
    __syncthreads();

    // r[q][d] = (q . relk[d]) * C2A  (stored bf16, pre-scaled for exp2)
    {
        int q = tid >> 1;
        int d0 = (tid & 1) * 17, nd = (tid & 1) ? 16 : 17;
        float qv[64];
#pragma unroll
        for (int e2 = 0; e2 < 32; e2++) {
            uint32_t hv = *(uint32_t*)(sm + AQH + q * 144 + e2 * 4);
            uint32_t lv = *(uint32_t*)(sm + AQL + q * 144 + e2 * 4);
            float2 fh = __bfloat1622float2(*(__nv_bfloat162*)&hv);
            float2 fl = __bfloat1622float2(*(__nv_bfloat162*)&lv);
            qv[2 * e2] = fh.x + fl.x;
            qv[2 * e2 + 1] = fh.y + fl.y;
        }
        for (int d = d0; d < d0 + nd; d++) {
            float s = 0.f;
#pragma unroll
            for (int e = 0; e < 64; e++) s += qv[e] * sRK[d * 64 + e];
            *(bf16*)(sm + ARB + (q * 33 + d) * 2) = __float2bfloat16_rn(s * C2A);
        }
    }
    __syncthreads();

    const int wm = w >> 1, wn = w & 1;
    float acc2[8][4];
#pragma unroll
    for (int j = 0; j < 8; j++)
#pragma unroll
        for (int r = 0; r < 4; r++) acc2[j][r] = 0.f;
    float lsum[4] = {0.f, 0.f, 0.f, 0.f};
    float wsuf[4] = {0.f, 0.f, 0.f, 0.f};

    for (int t = 0; t < 8; t++) {
        CP_WAIT(1);
        __syncthreads();

        // ---- QK phase ----
        float acc[2][8][4];
#pragma unroll
        for (int i = 0; i < 2; i++)
#pragma unroll
            for (int j = 0; j < 8; j++)
#pragma unroll
                for (int r = 0; r < 4; r++) acc[i][j][r] = 0.f;
#pragma unroll
        for (int es = 0; es < 4; es++) {
            uint32_t ah[2][4], al[2][4];
#pragma unroll
            for (int i = 0; i < 2; i++) {
                uint32_t ao = (uint32_t)((wm * 32 + i * 16 + lr) * 144) + hc + es * 32;
                LDSM4(ah[i], sb + AQH + ao);
                LDSM4(al[i], sb + AQL + ao);
            }
            uint32_t bh[8][2], bl[8][2];
#pragma unroll
            for (int c = 0; c < 4; c++) {
                uint32_t bo = (uint32_t)((wn * 64 + c * 16 + lr) * 144) + hc + es * 32;
                uint32_t r[4];
                LDSM4(r, sb + AKH + bo);
                bh[2*c][0] = r[0]; bh[2*c+1][0] = r[1];
                bh[2*c][1] = r[2]; bh[2*c+1][1] = r[3];
                LDSM4(r, sb + AKL + bo);
                bl[2*c][0] = r[0]; bl[2*c+1][0] = r[1];
                bl[2*c][1] = r[2]; bl[2*c+1][1] = r[3];
            }
#pragma unroll
            for (int i = 0; i < 2; i++)
#pragma unroll
                for (int j = 0; j < 8; j++) {
                    mma_bf16(acc[i][j], ah[i], bh[j]);
                    mma_bf16(acc[i][j], ah[i], bl[j]);
                    mma_bf16(acc[i][j], al[i], bh[j]);
                }
        }
        __syncthreads();
        if (t < 7) ldTile(AKH, AKL, Kh, Kl, t + 1);

        // ---- softmax epilogue -> P (bf16 hi/lo) ----
        const int k0 = t * 128;
        const int X = blockIdx.x;
        const int cls = (t + 2 <= X) ? 0 : ((t >= X + 2) ? 2 : 1);
        if (cls != 1) {
            float rbv[2][2];
#pragma unroll
            for (int i = 0; i < 2; i++)
#pragma unroll
                for (int rh = 0; rh < 2; rh++) {
                    int rr = wm * 32 + i * 16 + (lane >> 2) + rh * 8;
                    rbv[i][rh] = __bfloat162float(
                        *(bf16*)(sm + ARB + (rr * 33 + (cls == 2 ? 32 : 0)) * 2));
                }
#pragma unroll
            for (int i = 0; i < 2; i++)
#pragma unroll
                for (int j = 0; j < 8; j++) {
                    int col = wn * 64 + j * 8 + (lane & 3) * 2;
#pragma unroll
                    for (int rh = 0; rh < 2; rh++) {
                        int rr = wm * 32 + i * 16 + (lane >> 2) + rh * 8;
                        float p0 = exp2f(fmaf(acc[i][j][rh * 2 + 0], C2A, rbv[i][rh]));
                        float p1 = exp2f(fmaf(acc[i][j][rh * 2 + 1], C2A, rbv[i][rh]));
                        lsum[i * 2 + rh] += p0 + p1;
                        if (cls == 2) wsuf[i * 2 + rh] += p0 + p1;
                        uint32_t po = (uint32_t)(rr * 272 + col * 2);
                        *(uint32_t*)(sm + APH + po) = pack_hi(p0, p1);
                        *(uint32_t*)(sm + APL + po) = pack_lo(p0, p1);
                    }
                }
        } else {
#pragma unroll
            for (int i = 0; i < 2; i++)
#pragma unroll
                for (int j = 0; j < 8; j++) {
                    int col = wn * 64 + j * 8 + (lane & 3) * 2;
#pragma unroll
                    for (int rh = 0; rh < 2; rh++) {
                        int rr = wm * 32 + i * 16 + (lane >> 2) + rh * 8;
                        int qg = q0 + rr;
                        float p01[2];
#pragma unroll
                        for (int v = 0; v < 2; v++) {
                            int kg = k0 + col + v;
                            int dd = kg - qg;
                            int dc = dd < -16 ? -16 : (dd > 16 ? 16 : dd);
                            float rb = __bfloat162float(
                                *(bf16*)(sm + ARB + (rr * 33 + dc + 16) * 2));
                            float p = exp2f(fmaf(acc[i][j][rh * 2 + v], C2A, rb));
                            p01[v] = p;
                            lsum[i * 2 + rh] += p;
                            if (dd >= 16) wsuf[i * 2 + rh] += p;
                            else if (dd > -16) sW[rr * 33 + dd + 16] = p;
                        }
                        uint32_t po = (uint32_t)(rr * 272 + col * 2);
                        *(uint32_t*)(sm + APH + po) = pack_hi(p01[0], p01[1]);
                        *(uint32_t*)(sm + APL + po) = pack_lo(p01[0], p01[1]);
                    }
                }
        }
        if (t < 7) { CP_WAIT(1); } else { CP_WAIT(0); }
        __syncthreads();   // P visible + V[t] ready

        // ---- PV phase ----
#pragma unroll
        for (int ks = 0; ks < 8; ks++) {
            uint32_t ph[4], pl[4];
            uint32_t po = (uint32_t)((w * 16 + lr) * 272) + ks * 32 + hc;
            LDSM4(ph, sb + APH + po);
            LDSM4(pl, sb + APL + po);
            uint32_t vh[8][2], vl[8][2];
#pragma unroll
            for (int c = 0; c < 4; c++) {
                uint32_t vo = (uint32_t)((ks * 16 + lr) * 144) + (c * 2 + (lane >> 4)) * 16;
                uint32_t r[4];
                LDSM4T(r, sb + AVH + vo);
                vh[2*c][0] = r[0]; vh[2*c][1] = r[1];
                vh[2*c+1][0] = r[2]; vh[2*c+1][1] = r[3];
                LDSM4T(r, sb + AVL + vo);
                vl[2*c][0] = r[0]; vl[2*c][1] = r[1];
                vl[2*c+1][0] = r[2]; vl[2*c+1][1] = r[3];
            }
#pragma unroll
            for (int j = 0; j < 8; j++) {
                mma_bf16(acc2[j], ph, vh[j]);
                mma_bf16(acc2[j], ph, vl[j]);
                mma_bf16(acc2[j], pl, vh[j]);
            }
        }
        __syncthreads();
        if (t < 7) ldTile(AVH, AVL, Vh, Vl, t + 1);
    }

    // ---- deterministic l / w32 reduction ----
#pragma unroll
    for (int i = 0; i < 4; i++) {
        lsum[i] += __shfl_xor_sync(0xffffffffu, lsum[i], 1);
        lsum[i] += __shfl_xor_sync(0xffffffffu, lsum[i], 2);
        wsuf[i] += __shfl_xor_sync(0xffffffffu, wsuf[i], 1);
        wsuf[i] += __shfl_xor_sync(0xffffffffu, wsuf[i], 2);
    }
    if ((lane & 3) == 0) {
#pragma unroll
        for (int i = 0; i < 4; i++) {
            int row = wm * 32 + (i >> 1) * 16 + (i & 1) * 8 + (lane >> 2);
            sLp[row * 2 + wn] = lsum[i];
            sWp[row * 2 + wn] = wsuf[i];
        }
    }
    __syncthreads();
    if (tid < 128) {
        int r = tid;
        float l = sLp[r * 2] + sLp[r * 2 + 1];
        float ws = sWp[r * 2] + sWp[r * 2 + 1];
        float mid = 0.f;
#pragma unroll
        for (int d = 1; d < 32; d++) mid += sW[r * 33 + d];
        sW[r * 33 + 0] = l - ws - mid;
        sW[r * 33 + 32] = ws;
        sL[r] = 1.f / l;
    }
    __syncthreads();

    // ---- rel_v bias + normalize + store O (bf16 hi/lo, [B,S,HID]) ----
#pragma unroll
    for (int j = 0; j < 8; j++) {
        int row0 = w * 16 + (lane >> 2), row1 = row0 + 8;
        int col = j * 8 + (lane & 3) * 2;
        float b00 = 0.f, b01 = 0.f, b10 = 0.f, b11 = 0.f;
#pragma unroll
        for (int d = 0; d < 33; d++) {
            float w0v = sW[row0 * 33 + d], w1v = sW[row1 * 33 + d];
            float r0 = sRV[d * 64 + col], r1 = sRV[d * 64 + col + 1];
            b00 += w0v * r0; b01 += w0v * r1;
            b10 += w1v * r0; b11 += w1v * r1;
        }
        float il0 = sL[row0], il1 = sL[row1];
        float o00 = (acc2[j][0] + b00) * il0, o01 = (acc2[j][1] + b01) * il0;
        float o10 = (acc2[j][2] + b10) * il1, o11 = (acc2[j][3] + b11) * il1;
        size_t g0 = ((size_t)(blockIdx.z * 1024 + q0 + row0)) * 1024 + blockIdx.y * 64 + col;
        size_t g1 = ((size_t)(blockIdx.z * 1024 + q0 + row1)) * 1024 + blockIdx.y * 64 + col;
        *(uint32_t*)&Oh[g0] = pack_hi(o00, o01);
        *(uint32_t*)&Ol[g0] = pack_lo(o00, o01);
        *(uint32_t*)&Oh[g1] = pack_hi(o10, o11);
        *(uint32_t*)&Ol[g1] = pack_lo(o10, o11);
    }
}

// =================================================================
extern "C" void kernel_launch(void* const* d_in, const int* in_sizes, int n_in,
                              void* d_out, int out_size)
{
    const float* query = (const float*)d_in[0];
    const float* key   = (const float*)d_in[1];
    const float* value = (const float*)d_in[2];
    const float* Wq    = (const float*)d_in[3];
    const float* bq    = (const float*)d_in[4];
    const float* Wk    = (const float*)d_in[5];
    const float* bk    = (const float*)d_in[6];
    const float* Wv    = (const float*)d_in[7];
    const float* bv    = (const float*)d_in[8];
    const float* relk  = (const float*)d_in[9];
    const float* relv  = (const float*)d_in[10];
    const float* fcW   = (const float*)d_in[11];
    const float* fcb   = (const float*)d_in[12];
    float* out = (float*)d_out;

    bf16 *Qh, *Ql, *Kh, *Kl, *Vh, *Vl, *Oh, *Ol, *Wh, *Wl, *Bh, *Bl;
    cudaGetSymbolAddress((void**)&Qh, g_Qh); cudaGetSymbolAddress((void**)&Ql, g_Ql);
    cudaGetSymbolAddress((void**)&Kh, g_Kh); cudaGetSymbolAddress((void**)&Kl, g_Kl);
    cudaGetSymbolAddress((void**)&Vh, g_Vh); cudaGetSymbolAddress((void**)&Vl, g_Vl);
    cudaGetSymbolAddress((void**)&Oh, g_Oh); cudaGetSymbolAddress((void**)&Ol, g_Ol);
    cudaGetSymbolAddress((void**)&Wh, g_Wh); cudaGetSymbolAddress((void**)&Wl, g_Wl);
    cudaGetSymbolAddress((void**)&Bh, g_Bh); cudaGetSymbolAddress((void**)&Bl, g_Bl);

    cudaFuncSetAttribute(gemm_proj, cudaFuncAttributeMaxDynamicSharedMemorySize, GH_SMEM);
    cudaFuncSetAttribute(gemm_fc, cudaFuncAttributeMaxDynamicSharedMemorySize, GH_SMEM);
    cudaFuncSetAttribute(attn_hmma, cudaFuncAttributeMaxDynamicSharedMemorySize, ATT_SMEM);

    splitW3<<<dim3(32, 32, 3), 256>>>(Wq, Wk, Wv, Wh, Wl);
    split_f32<<<1024, 256>>>(fcW, Bh, Bl, 1024 * 1024);

    gemm_proj<<<dim3(8, 32, 3), 256, GH_SMEM>>>(query, key, value, Wh, Wl,
                                                bq, bk, bv,
                                                Qh, Ql, Kh, Kl, Vh, Vl);

    attn_hmma<<<dim3(8, NH, NB), 256, ATT_SMEM>>>(Qh, Ql, Kh, Kl, Vh, Vl,
                                                  relk, relv, Oh, Ol);

    gemm_fc<<<dim3(8, 32), 256, GH_SMEM>>>(Oh, Ol, Bh, Bl, fcb, out);
}